// round 12
// baseline (speedup 1.0000x reference)
#include <cuda_runtime.h>
#include <cuda_bf16.h>
#include <cstdint>

// MaxUnpooling2D scatter-add.
//   updates/mask: [B=16, H=128, W=128, C=64]  -> 16,777,216 elements
//   output:       [B=16, OH=256, OW=256, C=64] -> 67,108,864 floats (268 MB)
// out_idx = (b<<22) | (mask & ~63) | c   (channel comes from the source element)
//
// R12: GROUP=2 phased pipeline, but zero(g+1) and scatter(g) are fused at
// THREAD level: every thread issues its 2 input loads, then 4 independent
// zero STG.128 (to group g+1) inside the load-latency shadow, then its 4
// REDG atomics. Every wave of every kernel issues atomics, keeping the
// chip-wide REDG stream (the ~77us hard wall) continuously fed, instead of
// scatter-waves-then-zero-waves (R6's intra-kernel phasing).

static constexpr int B_DIM      = 16;
static constexpr int GROUP      = 2;
static constexpr int NGROUPS    = B_DIM / GROUP;              // 8
static constexpr int HWC        = 1 << 20;                    // elems per batch
static constexpr int OUT_PER_B  = 1 << 22;                    // out floats per batch

static constexpr int THREADS    = 256;

static constexpr int SQ_PER_G   = GROUP * HWC / 4;            // 524,288 quads / group
static constexpr int S_BLOCKS   = SQ_PER_G / THREADS;         // 2048 blocks / group

static constexpr int ZV_PER_G   = GROUP * OUT_PER_B / 4;      // 2,097,152 float4 / group
static constexpr int Z_PER_TH   = ZV_PER_G / (S_BLOCKS * THREADS);  // 4 float4 per thread
static constexpr int Z_STRIDE   = S_BLOCKS * THREADS;         // 524,288

static constexpr int Z_BLOCKS   = ZV_PER_G / THREADS;         // 8192 (prologue only)

// ---------------------------------------------------------------------------
// Fused: scatter group g + zero group g+1, all in every thread.
__global__ void __launch_bounds__(THREADS)
scatter_zero_kernel(const float4* __restrict__ upd4,
                    const int4*   __restrict__ msk4,
                    float* __restrict__ out_g,
                    float4* __restrict__ out4_next)
{
    int q  = blockIdx.x * THREADS + threadIdx.x;  // quad index in group
    int i  = q << 2;
    int bl = q >> 18;                             // batch within group
    int c  = i & 63;

    // 1) Long-latency input loads first.
    float4 u = __ldcs(&upd4[q]);
    int4   m = __ldcs(&msk4[q]);

    // 2) Independent zero stores ride the load-latency shadow.
    const float4 z = make_float4(0.f, 0.f, 0.f, 0.f);
    #pragma unroll
    for (int k = 0; k < Z_PER_TH; k++)
        out4_next[q + k * Z_STRIDE] = z;

    // 3) Atomic scatter (REDG, fire-and-forget).
    int base = bl << 22;
    atomicAdd(&out_g[base | (m.x & ~63) | (c + 0)], u.x);
    atomicAdd(&out_g[base | (m.y & ~63) | (c + 1)], u.y);
    atomicAdd(&out_g[base | (m.z & ~63) | (c + 2)], u.z);
    atomicAdd(&out_g[base | (m.w & ~63) | (c + 3)], u.w);
}

// Prologue: zero group 0 (plain STG, nothing to overlap with).
__global__ void __launch_bounds__(THREADS)
zero_kernel(float4* __restrict__ out4)
{
    out4[blockIdx.x * THREADS + threadIdx.x] = make_float4(0.f, 0.f, 0.f, 0.f);
}

// Epilogue: scatter only (last group).
__global__ void __launch_bounds__(THREADS)
scatter_kernel(const float4* __restrict__ upd4,
               const int4*   __restrict__ msk4,
               float* __restrict__ out_g)
{
    int q  = blockIdx.x * THREADS + threadIdx.x;
    int i  = q << 2;
    int bl = q >> 18;
    int c  = i & 63;

    float4 u = __ldcs(&upd4[q]);
    int4   m = __ldcs(&msk4[q]);

    int base = bl << 22;
    atomicAdd(&out_g[base | (m.x & ~63) | (c + 0)], u.x);
    atomicAdd(&out_g[base | (m.y & ~63) | (c + 1)], u.y);
    atomicAdd(&out_g[base | (m.z & ~63) | (c + 2)], u.z);
    atomicAdd(&out_g[base | (m.w & ~63) | (c + 3)], u.w);
}

// ---------------------------------------------------------------------------
extern "C" void kernel_launch(void* const* d_in, const int* in_sizes, int n_in,
                              void* d_out, int out_size)
{
    const float4* upd4 = (const float4*)d_in[0];
    const int4*   msk4 = (const int4*)d_in[1];
    float*        out  = (float*)d_out;

    const size_t GRP_QUADS = (size_t)SQ_PER_G;
    const size_t GRP_OUT   = (size_t)GROUP * OUT_PER_B;

    // Prologue: zero group 0.
    zero_kernel<<<Z_BLOCKS, THREADS>>>((float4*)out);

    // Steady state: thread-fused scatter(g) + zero(g+1).
    for (int g = 0; g < NGROUPS - 1; g++) {
        scatter_zero_kernel<<<S_BLOCKS, THREADS>>>(
            upd4 + (size_t)g * GRP_QUADS,
            msk4 + (size_t)g * GRP_QUADS,
            out  + (size_t)g * GRP_OUT,
            (float4*)(out + (size_t)(g + 1) * GRP_OUT));
    }

    // Epilogue: scatter last group.
    int g = NGROUPS - 1;
    scatter_kernel<<<S_BLOCKS, THREADS>>>(
        upd4 + (size_t)g * GRP_QUADS,
        msk4 + (size_t)g * GRP_QUADS,
        out  + (size_t)g * GRP_OUT);
}

// round 13
// speedup vs baseline: 1.1393x; 1.1393x over previous
#include <cuda_runtime.h>
#include <cuda_bf16.h>
#include <cstdint>

// MaxUnpooling2D scatter-add.
//   updates/mask: [B=16, H=128, W=128, C=64]  -> 16,777,216 elements
//   output:       [B=16, OH=256, OW=256, C=64] -> 67,108,864 floats (268 MB)
// out_idx = (b<<22) | (mask & ~63) | c   (channel comes from the source element)
//
// R13: R6/R10's proven phased recipe (GROUP=2, zero->scatter ordering via
// kernel boundaries, scatter blocks first, 1 quad/thread, STG zero, 9
// launches) + PDL (programmatic dependent launch) so each kernel's pre-sync
// phase (input loads, zero stores to region g+2) overlaps the previous
// kernel's atomic-drain tail. Atomics still execute only after
// cudaGridDependencySynchronize(), i.e. after zero(g) is complete+flushed.
// Stream-order drain exposure (~2-4us x 8 boundaries) is removed.

static constexpr int B_DIM      = 16;
static constexpr int GROUP      = 2;
static constexpr int NGROUPS    = B_DIM / GROUP;              // 8
static constexpr int HWC        = 1 << 20;                    // elems per batch
static constexpr int OUT_PER_B  = 1 << 22;                    // out floats per batch

static constexpr int THREADS    = 256;

static constexpr int SQ_PER_B   = HWC / 4;                    // 262,144 quads (1<<18)
static constexpr int SQ_PER_G   = GROUP * SQ_PER_B;           // 524,288 quads
static constexpr int S_BLOCKS   = SQ_PER_G / THREADS;         // 2048

static constexpr int ZV_PER_G   = GROUP * OUT_PER_B / 4;      // 2,097,152 float4
static constexpr int Z_BLOCKS   = ZV_PER_G / THREADS;         // 8192

// ---------------------------------------------------------------------------
// Scatter one group (2 batches); split into pre-sync (loads) and post-sync
// (atomics) around the PDL grid-dependency wait.
__device__ __forceinline__ void scatter_group_pdl(const float4* __restrict__ upd4,
                                                  const int4*   __restrict__ msk4,
                                                  float* __restrict__ out,
                                                  int sblk)
{
    int q  = sblk * THREADS + threadIdx.x;  // quad index in group
    int i  = q << 2;                        // element index in group
    int bl = q >> 18;                       // batch within group
    int c  = i & 63;                        // channel of first lane

    // Pre-sync: issue input loads (const data, never depends on prior kernel).
    float4 u = __ldcs(&upd4[q]);
    int4   m = __ldcs(&msk4[q]);

    // Allow the NEXT kernel to begin its pre-sync phase.
    cudaTriggerProgrammaticLaunchCompletion();

    // Wait for the PREVIOUS kernel (which zeroed this group) to complete+flush.
    cudaGridDependencySynchronize();

    int base = bl << 22;
    atomicAdd(&out[base | (m.x & ~63) | (c + 0)], u.x);
    atomicAdd(&out[base | (m.y & ~63) | (c + 1)], u.y);
    atomicAdd(&out[base | (m.z & ~63) | (c + 2)], u.z);
    atomicAdd(&out[base | (m.w & ~63) | (c + 3)], u.w);
}

__device__ __forceinline__ void zero_group(float4* __restrict__ out4, int zblk)
{
    // Zero blocks touch region g+1, disjoint from everything the previous
    // kernel wrote (regions g-1, g) -> no dependency sync needed.
    out4[zblk * THREADS + threadIdx.x] = make_float4(0.f, 0.f, 0.f, 0.f);
}

// ---------------------------------------------------------------------------
// Prologue: zero group 0. Trigger early so kernel 0's pre-sync phase overlaps.
__global__ void __launch_bounds__(THREADS)
zero_kernel(float4* __restrict__ out4)
{
    cudaTriggerProgrammaticLaunchCompletion();
    zero_group(out4, blockIdx.x);
}

// Fused: scatter group g (blocks [0, S_BLOCKS)) then zero group g+1.
__global__ void __launch_bounds__(THREADS)
scatter_zero_kernel(const float4* __restrict__ upd4,
                    const int4*   __restrict__ msk4,
                    float* __restrict__ out_g,
                    float4* __restrict__ out4_next)
{
    int blk = blockIdx.x;
    if (blk < S_BLOCKS) {
        scatter_group_pdl(upd4, msk4, out_g, blk);
    } else {
        cudaTriggerProgrammaticLaunchCompletion();
        zero_group(out4_next, blk - S_BLOCKS);
    }
}

// Epilogue: scatter only (last group).
__global__ void __launch_bounds__(THREADS)
scatter_kernel(const float4* __restrict__ upd4,
               const int4*   __restrict__ msk4,
               float* __restrict__ out_g)
{
    scatter_group_pdl(upd4, msk4, out_g, blockIdx.x);
}

// ---------------------------------------------------------------------------
template <typename... Args>
static void launch_pdl(void (*kern)(Args...), int blocks, Args... args)
{
    cudaLaunchConfig_t cfg = {};
    cfg.gridDim  = dim3((unsigned)blocks, 1, 1);
    cfg.blockDim = dim3(THREADS, 1, 1);
    cfg.dynamicSmemBytes = 0;
    cfg.stream = 0;
    cudaLaunchAttribute attr[1];
    attr[0].id = cudaLaunchAttributeProgrammaticStreamSerialization;
    attr[0].val.programmaticStreamSerializationAllowed = 1;
    cfg.attrs = attr;
    cfg.numAttrs = 1;
    cudaLaunchKernelEx(&cfg, kern, args...);
}

extern "C" void kernel_launch(void* const* d_in, const int* in_sizes, int n_in,
                              void* d_out, int out_size)
{
    const float4* upd4 = (const float4*)d_in[0];
    const int4*   msk4 = (const int4*)d_in[1];
    float*        out  = (float*)d_out;

    const size_t GRP_QUADS = (size_t)SQ_PER_G;
    const size_t GRP_OUT   = (size_t)GROUP * OUT_PER_B;

    // Prologue: zero group 0 (first kernel: plain launch, no dependency).
    zero_kernel<<<Z_BLOCKS, THREADS>>>((float4*)out);

    // Steady state: scatter(g) then zero(g+1), each launch PDL-dependent on
    // the previous so pre-sync phases overlap upstream drain tails.
    for (int g = 0; g < NGROUPS - 1; g++) {
        launch_pdl(scatter_zero_kernel, S_BLOCKS + Z_BLOCKS,
                   upd4 + (size_t)g * GRP_QUADS,
                   msk4 + (size_t)g * GRP_QUADS,
                   out  + (size_t)g * GRP_OUT,
                   (float4*)(out + (size_t)(g + 1) * GRP_OUT));
    }

    // Epilogue: scatter last group.
    int g = NGROUPS - 1;
    launch_pdl(scatter_kernel, S_BLOCKS,
               upd4 + (size_t)g * GRP_QUADS,
               msk4 + (size_t)g * GRP_QUADS,
               out  + (size_t)g * GRP_OUT);
}

// round 14
// speedup vs baseline: 1.1868x; 1.0417x over previous
#include <cuda_runtime.h>
#include <cuda_bf16.h>
#include <cstdint>

// MaxUnpooling2D scatter-add.
//   updates/mask: [B=16, H=128, W=128, C=64]  -> 16,777,216 elements
//   output:       [B=16, OH=256, OW=256, C=64] -> 67,108,864 floats (268 MB)
// out_idx = (b<<22) | (mask & ~63) | c   (channel comes from the source element)
//
// R14: R6/R10's proven phased structure (GROUP=2, zero->scatter via kernel
// boundaries, scatter blocks first), single change: per-thread work depth x2
// in BOTH roles (no role interleave):
//   scatter: 2 quads/thread, 4 front-batched LDG.128 -> 8 REDG
//   zero:    2 float4/thread
// Grid 10240 -> 5120 blocks/group: better latency hiding, less tail
// quantization, same phased semantics.

static constexpr int B_DIM      = 16;
static constexpr int GROUP      = 2;
static constexpr int NGROUPS    = B_DIM / GROUP;              // 8
static constexpr int HWC        = 1 << 20;                    // elems per batch
static constexpr int OUT_PER_B  = 1 << 22;                    // out floats per batch

static constexpr int THREADS    = 256;

static constexpr int SQ_PER_G   = GROUP * HWC / 4;            // 524,288 quads / group
static constexpr int S_TH       = SQ_PER_G / 2;               // 262,144 scatter threads
static constexpr int S_BLOCKS   = S_TH / THREADS;             // 1024

static constexpr int ZV_PER_G   = GROUP * OUT_PER_B / 4;      // 2,097,152 float4 / group
static constexpr int Z_TH       = ZV_PER_G / 2;               // 1,048,576 zero threads
static constexpr int Z_BLOCKS   = Z_TH / THREADS;             // 4096

// ---------------------------------------------------------------------------
// Scatter one group: thread t handles quads t and t+S_TH.
// S_TH quads = 1<<18 = exactly one batch worth, so quad t is batch 0 of the
// group and quad t+S_TH is batch 1; channel bits identical for both.
__device__ __forceinline__ void scatter_group(const float4* __restrict__ upd4,
                                              const int4*   __restrict__ msk4,
                                              float* __restrict__ out,
                                              int sblk)
{
    int t = sblk * THREADS + threadIdx.x;   // 0 .. 262,143
    int c = (t << 2) & 63;                  // channel of first lane (same for both quads)

    // Front-batch all 4 wide loads (8 outstanding sectors) for MLP.
    float4 u0 = __ldg(&upd4[t]);
    int4   m0 = __ldg(&msk4[t]);
    float4 u1 = __ldg(&upd4[t + S_TH]);
    int4   m1 = __ldg(&msk4[t + S_TH]);

    float* out0 = out;                      // batch 0 region
    float* out1 = out + OUT_PER_B;          // batch 1 region

    atomicAdd(&out0[(m0.x & ~63) | (c + 0)], u0.x);
    atomicAdd(&out0[(m0.y & ~63) | (c + 1)], u0.y);
    atomicAdd(&out0[(m0.z & ~63) | (c + 2)], u0.z);
    atomicAdd(&out0[(m0.w & ~63) | (c + 3)], u0.w);

    atomicAdd(&out1[(m1.x & ~63) | (c + 0)], u1.x);
    atomicAdd(&out1[(m1.y & ~63) | (c + 1)], u1.y);
    atomicAdd(&out1[(m1.z & ~63) | (c + 2)], u1.z);
    atomicAdd(&out1[(m1.w & ~63) | (c + 3)], u1.w);
}

// Zero one group's output region: 2 float4 per thread, coalesced strided.
__device__ __forceinline__ void zero_group(float4* __restrict__ out4, int zblk)
{
    int t = zblk * THREADS + threadIdx.x;   // 0 .. 1,048,575
    const float4 z = make_float4(0.f, 0.f, 0.f, 0.f);
    out4[t]        = z;
    out4[t + Z_TH] = z;
}

// ---------------------------------------------------------------------------
__global__ void __launch_bounds__(THREADS)
zero_kernel(float4* __restrict__ out4)
{
    zero_group(out4, blockIdx.x);
}

// Fused: scatter group g (blocks [0, S_BLOCKS)) then zero group g+1.
__global__ void __launch_bounds__(THREADS)
scatter_zero_kernel(const float4* __restrict__ upd4,
                    const int4*   __restrict__ msk4,
                    float* __restrict__ out_g,
                    float4* __restrict__ out4_next)
{
    int blk = blockIdx.x;
    if (blk < S_BLOCKS) {
        scatter_group(upd4, msk4, out_g, blk);
    } else {
        zero_group(out4_next, blk - S_BLOCKS);
    }
}

__global__ void __launch_bounds__(THREADS)
scatter_kernel(const float4* __restrict__ upd4,
               const int4*   __restrict__ msk4,
               float* __restrict__ out_g)
{
    scatter_group(upd4, msk4, out_g, blockIdx.x);
}

// ---------------------------------------------------------------------------
extern "C" void kernel_launch(void* const* d_in, const int* in_sizes, int n_in,
                              void* d_out, int out_size)
{
    const float4* upd4 = (const float4*)d_in[0];
    const int4*   msk4 = (const int4*)d_in[1];
    float*        out  = (float*)d_out;

    const size_t GRP_QUADS = (size_t)SQ_PER_G;
    const size_t GRP_OUT   = (size_t)GROUP * OUT_PER_B;

    // Prologue: zero group 0.
    zero_kernel<<<Z_BLOCKS, THREADS>>>((float4*)out);

    // Steady state: scatter(g) then zero(g+1), phased by block order.
    for (int g = 0; g < NGROUPS - 1; g++) {
        scatter_zero_kernel<<<S_BLOCKS + Z_BLOCKS, THREADS>>>(
            upd4 + (size_t)g * GRP_QUADS,
            msk4 + (size_t)g * GRP_QUADS,
            out  + (size_t)g * GRP_OUT,
            (float4*)(out + (size_t)(g + 1) * GRP_OUT));
    }

    // Epilogue: scatter last group.
    int g = NGROUPS - 1;
    scatter_kernel<<<S_BLOCKS, THREADS>>>(
        upd4 + (size_t)g * GRP_QUADS,
        msk4 + (size_t)g * GRP_QUADS,
        out  + (size_t)g * GRP_OUT);
}

// round 15
// speedup vs baseline: 1.2275x; 1.0343x over previous
#include <cuda_runtime.h>
#include <cuda_bf16.h>
#include <cstdint>

// MaxUnpooling2D scatter-add.
//   updates/mask: [B=16, H=128, W=128, C=64]  -> 16,777,216 elements
//   output:       [B=16, OH=256, OW=256, C=64] -> 67,108,864 floats (268 MB)
// out_idx = (b<<22) | (mask & ~63) | c   (channel comes from the source element)
//
// R15: two independent zero->scatter pipelines on two capture-forked streams.
// True dependency graph is only zero(b) -> scatter(b); batches are mutually
// independent. Even batches run on the capture (default) stream, odd batches
// on a forked stream. The HW concurrent-kernel scheduler backfills across
// streams, so one pipeline's scatter (REDG-heavy) overlaps the other's zero
// (DRAM-heavy) and per-boundary atomic-drain tails are covered -- without
// static role interleave (condemned R3/R4/R12), software barriers (R5), or
// PDL block-parking (R13). Kernel bodies identical to the proven R6 shapes.
// L2 footprint: <= 4 active 16.7MB regions ~ 67MB < 126MB L2.

static constexpr int B_DIM     = 16;
static constexpr int HWC       = 1 << 20;             // elems per batch
static constexpr int OUT_PER_B = 1 << 22;             // out floats per batch
static constexpr int THREADS   = 256;

static constexpr int SQ_PER_B  = HWC / 4;             // 262,144 quads per batch
static constexpr int S_BLOCKS  = SQ_PER_B / THREADS;  // 1024
static constexpr int ZV_PER_B  = OUT_PER_B / 4;       // 1,048,576 float4 per batch
static constexpr int Z_BLOCKS  = ZV_PER_B / THREADS;  // 4096

// ---------------------------------------------------------------------------
__global__ void __launch_bounds__(THREADS)
zero_kernel(float4* __restrict__ out4)
{
    out4[blockIdx.x * THREADS + threadIdx.x] = make_float4(0.f, 0.f, 0.f, 0.f);
}

__global__ void __launch_bounds__(THREADS)
scatter_kernel(const float4* __restrict__ upd4,
               const int4*   __restrict__ msk4,
               float* __restrict__ out_b)
{
    int q = blockIdx.x * THREADS + threadIdx.x;   // quad index in batch
    int c = (q << 2) & 63;                        // channel of first lane

    float4 u = __ldg(&upd4[q]);
    int4   m = __ldg(&msk4[q]);

    atomicAdd(&out_b[(m.x & ~63) | (c + 0)], u.x);
    atomicAdd(&out_b[(m.y & ~63) | (c + 1)], u.y);
    atomicAdd(&out_b[(m.z & ~63) | (c + 2)], u.z);
    atomicAdd(&out_b[(m.w & ~63) | (c + 3)], u.w);
}

// ---------------------------------------------------------------------------
extern "C" void kernel_launch(void* const* d_in, const int* in_sizes, int n_in,
                              void* d_out, int out_size)
{
    const float4* upd4 = (const float4*)d_in[0];
    const int4*   msk4 = (const int4*)d_in[1];
    float*        out  = (float*)d_out;

    // Host-side objects, created once (host resources only; no device memory
    // allocation; identical GPU work on every call).
    static cudaStream_t s2 = nullptr;
    static cudaEvent_t  ev_fork = nullptr, ev_join = nullptr;
    if (s2 == nullptr) {
        cudaStreamCreateWithFlags(&s2, cudaStreamNonBlocking);
        cudaEventCreateWithFlags(&ev_fork, cudaEventDisableTiming);
        cudaEventCreateWithFlags(&ev_join, cudaEventDisableTiming);
    }

    // Fork: make s2 part of the capture, dependent on the capture stream head.
    cudaEventRecord(ev_fork, 0);
    cudaStreamWaitEvent(s2, ev_fork, 0);

    // Two independent pipelines: even batches on stream 0, odd on s2.
    // Each pipeline: zero(b); scatter(b); zero(b+2); scatter(b+2); ...
    for (int b = 0; b < B_DIM; b++) {
        cudaStream_t st = (b & 1) ? s2 : (cudaStream_t)0;
        float* out_b = out + (size_t)b * OUT_PER_B;

        zero_kernel<<<Z_BLOCKS, THREADS, 0, st>>>((float4*)out_b);
        scatter_kernel<<<S_BLOCKS, THREADS, 0, st>>>(
            upd4 + (size_t)b * SQ_PER_B,
            msk4 + (size_t)b * SQ_PER_B,
            out_b);
    }

    // Join: capture stream waits for the forked pipeline.
    cudaEventRecord(ev_join, s2);
    cudaStreamWaitEvent((cudaStream_t)0, ev_join, 0);
}